// round 14
// baseline (speedup 1.0000x reference)
#include <cuda_runtime.h>
#include <cstdint>

// ---------------- problem constants ----------------
#define NB    32
#define NC    64
#define HW    56
#define OHW   57
#define LL    3249           // 57*57
#define PP    256            // C*ks*ks
#define NROWS 103968         // NB*LL
#define KCL   512
#define PLSZ  831744         // PP*LL

// ---------------- scratch ----------------
__device__ float g_cols  [26615808];  // flat [NROWS][256] == [NB][PP][LL], tf32-rounded
__device__ float g_finalT[26615808];  // masked final, [NB][LL][256]  (l rows, p contiguous)
__device__ float g_S     [53231616];  // [NROWS][512] softmax weights (tf32-rounded)
__device__ float g_x2    [NROWS];
__device__ float g_c2    [KCL];
__device__ float g_centT [131072];    // centers^T [256][512] rounded (GEMM2 B: [n=p][k=cl])
__device__ float g_centR [131072];    // centers   [512][256] rounded (GEMM1 B: [n=cl][k=p])
__device__ float g_wR    [32768];     // weight [128][256] rounded    (GEMM3 A)

// ---------------- fast math ----------------
__device__ __forceinline__ float fast_sqrtf(float q) {
    float r = __int_as_float(0x5f3759df - (__float_as_int(q) >> 1));
    r = r * fmaf(-0.5f * q, r * r, 1.5f);
    r = r * fmaf(-0.5f * q, r * r, 1.5f);
    r = r * fmaf(-0.5f * q, r * r, 1.5f);
    float s = q * r;
    return (q > 1e-20f) ? s : 0.0f;
}
__device__ __forceinline__ float fast_expf(float x) {
    x = fmaxf(x, -80.0f);
    float y  = x * 1.44269504088896f;
    float t  = y + 12582912.0f;
    float f  = y - (t - 12582912.0f);
    int   e  = (__float_as_int(t) & 0x7FFFFF) - 0x400000;
    float p  = 1.3333558146e-3f;
    p = fmaf(p, f, 9.6180905e-3f);
    p = fmaf(p, f, 5.5504108665e-2f);
    p = fmaf(p, f, 2.4022650696e-1f);
    p = fmaf(p, f, 6.9314718056e-1f);
    p = fmaf(p, f, 1.0f);
    return p * __int_as_float((e + 127) << 23);
}
__device__ __forceinline__ uint32_t tf32cvt(float x) {
    uint32_t r; asm("cvt.rna.tf32.f32 %0, %1;" : "=r"(r) : "f"(x)); return r;
}
__device__ __forceinline__ float tf32r(float x) { return __uint_as_float(tf32cvt(x)); }

__device__ __forceinline__ void mma_tf32(float* c, const uint32_t* a, uint32_t b0, uint32_t b1) {
    asm volatile("mma.sync.aligned.m16n8k8.row.col.f32.tf32.tf32.f32 "
        "{%0,%1,%2,%3}, {%4,%5,%6,%7}, {%8,%9}, {%0,%1,%2,%3};"
        : "+f"(c[0]), "+f"(c[1]), "+f"(c[2]), "+f"(c[3])
        : "r"(a[0]), "r"(a[1]), "r"(a[2]), "r"(a[3]), "r"(b0), "r"(b1));
}

// ---------------- kernel 1: unfold (warp per flat row) ----------------
__global__ void k_unfold(const float* __restrict__ x) {
    int row = blockIdx.x * 8 + (threadIdx.x >> 5);
    int lane = threadIdx.x & 31;
    float s = 0.f;
    #pragma unroll
    for (int i = 0; i < 8; i++) {
        unsigned g = (unsigned)row * 256u + lane + 32u * i;
        unsigned b   = g / PLSZ;
        unsigned rem = g - b * PLSZ;
        unsigned p   = rem / LL;
        unsigned l   = rem - p * LL;
        unsigned c  = p >> 2, ki = (p >> 1) & 1u, kj = p & 1u;
        unsigned oi = l / OHW, oj = l - oi * OHW;
        int r  = (int)(oi + ki) - 1;
        int cc = (int)(oj + kj) - 1;
        float v = 0.0f;
        if ((unsigned)r < HW && (unsigned)cc < HW)
            v = x[(((b * NC + c) * HW + (unsigned)r) * HW + (unsigned)cc)];
        v = tf32r(v);
        g_cols[g] = v;
        s = fmaf(v, v, s);
    }
    #pragma unroll
    for (int o = 16; o; o >>= 1) s += __shfl_xor_sync(0xffffffffu, s, o);
    if (lane == 0) g_x2[row] = s;
}

// ---------------- kernel 2: |c|^2 ----------------
__global__ void k_c2(const float* __restrict__ cent) {
    int k = blockIdx.x * 8 + (threadIdx.x >> 5);
    int lane = threadIdx.x & 31;
    float s = 0.0f;
    #pragma unroll
    for (int i = 0; i < 8; i++) {
        float v = tf32r(cent[k * 256 + lane + 32 * i]);
        s = fmaf(v, v, s);
    }
    #pragma unroll
    for (int o = 16; o; o >>= 1) s += __shfl_xor_sync(0xffffffffu, s, o);
    if (lane == 0) g_c2[k] = s;
}

// ---------------- kernel 2b: rounded copy + transpose of centers ----------------
__global__ void k_tr(const float* __restrict__ cent) {
    __shared__ float t[32][33];
    int k0 = blockIdx.x * 32, j0 = blockIdx.y * 32;
    int tx = threadIdx.x & 31, ty = threadIdx.x >> 5;
    #pragma unroll
    for (int i = 0; i < 4; i++) {
        float v = tf32r(cent[(k0 + ty + 8 * i) * 256 + j0 + tx]);
        t[ty + 8 * i][tx] = v;
        g_centR[(k0 + ty + 8 * i) * 256 + j0 + tx] = v;
    }
    __syncthreads();
    #pragma unroll
    for (int i = 0; i < 4; i++)
        g_centT[(j0 + ty + 8 * i) * 512 + k0 + tx] = t[tx][ty + 8 * i];
}

// ---------------- kernel 2c: rounded copy of conv weight ----------------
__global__ void k_rw(const float* __restrict__ w) {
    int i = blockIdx.x * 256 + threadIdx.x;
    g_wR[i] = tf32r(w[i]);
}

// ---------------- unified tf32 mma.sync GEMM (512 thr, ldmatrix frags) ----------------
// A [m][k] row-major, B [n][k] row-major. smem [row][32k], swizzle k4 ^= (row&7);
// fragments via ldmatrix.m8n8.x4.b16.
// MODE 1: fused GEMM1+softmax. MT=64, NBLK=512, STG=3. grid(1625).
// MODE 2: MT=64, NBLK=256, STG=2. grid(1,1625). 2 CTA/SM. -> blend+mask -> g_finalT.
// MODE 3: MT=64, NBLK=256, STG=2. grid(13,64). bb=y>>1, m0=(y&1)*64. -> out+bias.
template<int MT, int NBLK, int KTOT, int MODE, int STG>
__global__ __launch_bounds__(512) void k_mma(const float* __restrict__ temp_p,
                                             const float* __restrict__ bias,
                                             float* __restrict__ out)
{
    constexpr int NCH = KTOT / 32;
    constexpr int AFL = MT * 32;
    constexpr int BFL = NBLK * 32;
    constexpr int WM = MT / 32, WN = 16 / WM;
    constexpr int NTW = NBLK / (WN * 8);
    constexpr int AU = (MT * 8) / 512;
    constexpr int BU = (NBLK * 8) / 512;
    extern __shared__ float sm[];

    const int tid = threadIdx.x;
    const int lane = tid & 31, wid = tid >> 5;
    const int warp_m = wid % WM, warp_n = wid / WM;
    const int g = lane >> 2, kq = lane & 3;

    const int n0 = (MODE == 2) ? blockIdx.x * NBLK : 0;   // MODE1 n0=0; MODE3 n0 from x below
    const int n0m3 = blockIdx.x * NBLK;
    const int m0 = (MODE == 1) ? blockIdx.x * MT
                 : (MODE == 2) ? blockIdx.y * MT
                 : (blockIdx.y & 1) * 64;
    const int bb = (MODE == 3) ? (blockIdx.y >> 1) : 0;
    const int nbase = (MODE == 3) ? n0m3 : n0;

    const float* Aptr = (MODE == 1) ? g_cols : (MODE == 2) ? g_S : g_wR;
    const float* Bptr = (MODE == 1) ? g_centR : (MODE == 2) ? g_centT
                                              : g_finalT + (size_t)bb * PLSZ;

    const uint32_t sA = (uint32_t)__cvta_generic_to_shared(sm);
    const uint32_t sB = sA + STG * AFL * 4;
    float* tail = sm + STG * (AFL + BFL);      // MODE1: c2s[512] + red[1024]

    if constexpr (MODE == 1)
        for (int i = tid; i < 512; i += 512) tail[i] = g_c2[i];

    float acc[2][NTW][4];
    #pragma unroll
    for (int mt = 0; mt < 2; mt++)
        #pragma unroll
        for (int nt = 0; nt < NTW; nt++)
            #pragma unroll
            for (int e = 0; e < 4; e++) acc[mt][nt][e] = 0.0f;

    auto load_stage = [&](int c) {
        const int stg = c % STG;
        #pragma unroll
        for (int i = 0; i < AU; i++) {
            int f = tid + i * 512;
            int row = f >> 3, k4 = f & 7;
            uint32_t dst = sA + (uint32_t)(stg * AFL + row * 32 + ((k4 ^ (row & 7)) << 2)) * 4u;
            int m = m0 + row;
            bool ok = (MODE == 3) || (m < NROWS);
            const float* src = ok ? (Aptr + (size_t)m * KTOT + c * 32 + k4 * 4) : Aptr;
            int sz = ok ? 16 : 0;
            asm volatile("cp.async.cg.shared.global [%0], [%1], 16, %2;"
                         :: "r"(dst), "l"(src), "r"(sz) : "memory");
        }
        #pragma unroll
        for (int i = 0; i < BU; i++) {
            int f = tid + i * 512;
            int row = f >> 3, k4 = f & 7;
            uint32_t dst = sB + (uint32_t)(stg * BFL + row * 32 + ((k4 ^ (row & 7)) << 2)) * 4u;
            int n = nbase + row;
            bool ok = (MODE != 3) || (n < LL);
            const float* src = ok ? (Bptr + (size_t)n * KTOT + c * 32 + k4 * 4) : Bptr;
            int sz = ok ? 16 : 0;
            asm volatile("cp.async.cg.shared.global [%0], [%1], 16, %2;"
                         :: "r"(dst), "l"(src), "r"(sz) : "memory");
        }
        asm volatile("cp.async.commit_group;" ::: "memory");
    };

    auto compute = [&](int c) {
        const uint32_t Ab = sA + (uint32_t)((c % STG) * AFL) * 4u;
        const uint32_t Bb = sB + (uint32_t)((c % STG) * BFL) * 4u;
        const int arow_base = warp_m * 32 + (lane & 15);
        const int a_hi = lane >> 4;
        const int brow_lane = lane & 7;
        const int b_grp_hi = lane >> 4;
        const int b_k_hi = (lane >> 3) & 1;
        #pragma unroll
        for (int s = 0; s < 4; s++) {
            uint32_t af[2][4];
            #pragma unroll
            for (int mt = 0; mt < 2; mt++) {
                int row = arow_base + mt * 16;
                int k4 = 2 * s + a_hi;
                uint32_t addr = Ab + (uint32_t)(row * 32 + ((k4 ^ (row & 7)) << 2)) * 4u;
                asm volatile("ldmatrix.sync.aligned.m8n8.x4.shared.b16 {%0,%1,%2,%3}, [%4];"
                    : "=r"(af[mt][0]), "=r"(af[mt][1]), "=r"(af[mt][2]), "=r"(af[mt][3])
                    : "r"(addr));
            }
            uint32_t bf[NTW][2];
            #pragma unroll
            for (int p2 = 0; p2 < NTW / 2; p2++) {
                int n = warp_n * (NTW * 8) + (2 * p2 + b_grp_hi) * 8 + brow_lane;
                int k4 = 2 * s + b_k_hi;
                uint32_t addr = Bb + (uint32_t)(n * 32 + ((k4 ^ (n & 7)) << 2)) * 4u;
                asm volatile("ldmatrix.sync.aligned.m8n8.x4.shared.b16 {%0,%1,%2,%3}, [%4];"
                    : "=r"(bf[2 * p2][0]), "=r"(bf[2 * p2][1]),
                      "=r"(bf[2 * p2 + 1][0]), "=r"(bf[2 * p2 + 1][1])
                    : "r"(addr));
            }
            #pragma unroll
            for (int mt = 0; mt < 2; mt++)
                #pragma unroll
                for (int g8 = 0; g8 < NTW; g8++)
                    mma_tf32(acc[mt][g8], af[mt], bf[g8][0], bf[g8][1]);
        }
    };

    if constexpr (STG == 3) {
        load_stage(0); load_stage(1);
        for (int c = 0; c < NCH; c++) {
            if (c + 2 < NCH) {
                load_stage(c + 2);
                asm volatile("cp.async.wait_group 2;" ::: "memory");
            } else {
                asm volatile("cp.async.wait_group 0;" ::: "memory");
            }
            __syncthreads();
            compute(c);
            __syncthreads();
        }
    } else {  // STG == 2: load-after-compute; exposed waits covered by co-resident CTA
        load_stage(0);
        load_stage(1);
        for (int c = 0; c < NCH; c++) {
            if (c + 1 < NCH) {
                asm volatile("cp.async.wait_group 1;" ::: "memory");
            } else {
                asm volatile("cp.async.wait_group 0;" ::: "memory");
            }
            __syncthreads();
            compute(c);
            __syncthreads();
            if (c + 2 < NCH) load_stage(c + 2);
        }
    }

    // ---------------- epilogues ----------------
    if constexpr (MODE == 1) {
        const float temp = *temp_p;
        float* c2s = tail;
        float* redm = tail + 512;        // [64 rows][8 warp_n]
        float* reds = tail + 1024;
        #pragma unroll
        for (int mt = 0; mt < 2; mt++)
            #pragma unroll
            for (int half = 0; half < 2; half++) {
                int rloc = warp_m * 32 + mt * 16 + g + 8 * half;
                int r = m0 + rloc;
                float x2 = (r < NROWS) ? g_x2[r] : 0.f;
                float mx = -1e30f;
                #pragma unroll
                for (int nt = 0; nt < NTW; nt++)
                    #pragma unroll
                    for (int e = 0; e < 2; e++) {
                        int col = warp_n * (NTW * 8) + nt * 8 + kq * 2 + e;
                        float q = fmaxf(fmaf(-2.f, acc[mt][nt][half * 2 + e], x2 + c2s[col]), 0.f);
                        float sc = -fast_sqrtf(q) * temp;
                        acc[mt][nt][half * 2 + e] = sc;
                        mx = fmaxf(mx, sc);
                    }
                mx = fmaxf(mx, __shfl_xor_sync(0xffffffffu, mx, 1));
                mx = fmaxf(mx, __shfl_xor_sync(0xffffffffu, mx, 2));
                if (kq == 0) redm[rloc * 8 + warp_n] = mx;
            }
        __syncthreads();
        #pragma unroll
        for (int mt = 0; mt < 2; mt++)
            #pragma unroll
            for (int half = 0; half < 2; half++) {
                int rloc = warp_m * 32 + mt * 16 + g + 8 * half;
                float m8 = -1e30f;
                #pragma unroll
                for (int j = 0; j < 8; j++) m8 = fmaxf(m8, redm[rloc * 8 + j]);
                float sum = 0.f;
                #pragma unroll
                for (int nt = 0; nt < NTW; nt++)
                    #pragma unroll
                    for (int e = 0; e < 2; e++) {
                        float v = fast_expf(acc[mt][nt][half * 2 + e] - m8);
                        acc[mt][nt][half * 2 + e] = v;
                        sum += v;
                    }
                sum += __shfl_xor_sync(0xffffffffu, sum, 1);
                sum += __shfl_xor_sync(0xffffffffu, sum, 2);
                if (kq == 0) reds[rloc * 8 + warp_n] = sum;
            }
        __syncthreads();
        #pragma unroll
        for (int mt = 0; mt < 2; mt++)
            #pragma unroll
            for (int half = 0; half < 2; half++) {
                int rloc = warp_m * 32 + mt * 16 + g + 8 * half;
                int r = m0 + rloc;
                if (r >= NROWS) continue;
                float denom = 0.f;
                #pragma unroll
                for (int j = 0; j < 8; j++) denom += reds[rloc * 8 + j];
                float inv = 1.0f / denom;
                #pragma unroll
                for (int nt = 0; nt < NTW; nt++) {
                    int col = warp_n * (NTW * 8) + nt * 8 + kq * 2;
                    float2 v = make_float2(tf32r(acc[mt][nt][half * 2] * inv),
                                           tf32r(acc[mt][nt][half * 2 + 1] * inv));
                    *(float2*)&g_S[(size_t)r * 512 + col] = v;
                }
            }
    } else if constexpr (MODE == 2) {
        const float temp = *temp_p;
        const float wT = temp / (temp + 1.0f), wF = 1.0f / (temp + 1.0f);
        #pragma unroll
        for (int mt = 0; mt < 2; mt++)
            #pragma unroll
            for (int half = 0; half < 2; half++) {
                int r = m0 + (warp_m * 2 + mt) * 16 + g + 8 * half;
                if (r >= NROWS) continue;
                unsigned rl = (unsigned)r % LL;
                unsigned b  = (unsigned)r / LL;
                size_t dstb = (size_t)b * PLSZ;
                #pragma unroll
                for (int nt = 0; nt < NTW; nt++) {
                    int j = nbase + warp_n * (NTW * 8) + nt * 8 + kq * 2;
                    #pragma unroll
                    for (int e = 0; e < 2; e++) {
                        unsigned rem = rl * 256u + (unsigned)(j + e);
                        unsigned p = rem / LL;
                        unsigned l = rem - p * LL;
                        unsigned lm = l % OHW;
                        unsigned ki = (p >> 1) & 1u, kj = p & 1u;
                        bool masked = (ki == 0u && l < OHW) || (ki == 1u && l >= 3192u) ||
                                      (kj == 0u && lm == 0u) || (kj == 1u && lm == 56u);
                        float av = acc[mt][nt][half * 2 + e];
                        float val = masked ? 0.0f
                            : fmaf(wT, av, wF * g_cols[(size_t)r * 256 + j + e]);
                        g_finalT[dstb + (size_t)l * 256 + p] = tf32r(val);
                    }
                }
            }
    } else {
        #pragma unroll
        for (int mt = 0; mt < 2; mt++)
            #pragma unroll
            for (int half = 0; half < 2; half++) {
                int oc = m0 + (warp_m * 2 + mt) * 16 + g + 8 * half;
                float bs = bias[oc];
                #pragma unroll
                for (int nt = 0; nt < NTW; nt++) {
                    int l = nbase + warp_n * (NTW * 8) + nt * 8 + kq * 2;
                    #pragma unroll
                    for (int e = 0; e < 2; e++) {
                        if (l + e < LL)
                            out[((size_t)bb * 128 + oc) * LL + l + e] =
                                acc[mt][nt][half * 2 + e] + bs;
                    }
                }
            }
    }
}

// ---------------- launcher ----------------
extern "C" void kernel_launch(void* const* d_in, const int* in_sizes, int n_in,
                              void* d_out, int out_size) {
    const float* x    = (const float*)d_in[0];
    const float* w    = (const float*)d_in[1];
    const float* bias = (const float*)d_in[2];
    const float* cent = (const float*)d_in[3];
    const float* temp = (const float*)d_in[4];
    float* out = (float*)d_out;

    const int SM1  = 3 * (64 * 32 + 512 * 32) * 4 + 6144;   // 227328
    const int SM23 = 2 * (64 * 32 + 256 * 32) * 4;           // 81920 -> 2 CTAs/SM
    cudaFuncSetAttribute(k_mma<64, 512, 256, 1, 3>,
                         cudaFuncAttributeMaxDynamicSharedMemorySize, SM1);
    cudaFuncSetAttribute(k_mma<64, 256, 512, 2, 2>,
                         cudaFuncAttributeMaxDynamicSharedMemorySize, SM23);
    cudaFuncSetAttribute(k_mma<64, 256, 256, 3, 2>,
                         cudaFuncAttributeMaxDynamicSharedMemorySize, SM23);

    k_unfold<<<12996, 256>>>(x);
    k_c2<<<64, 256>>>(cent);
    k_tr<<<dim3(16, 8), 256>>>(cent);
    k_mma<64, 512, 256, 1, 3><<<1625, 512, SM1>>>(temp, bias, out);   // profiled slot
    k_rw<<<128, 256>>>(w);
    k_mma<64, 256, 512, 2, 2><<<dim3(1, 1625), 512, SM23>>>(temp, bias, out);
    k_mma<64, 256, 256, 3, 2><<<dim3(13, 64), 512, SM23>>>(temp, bias, out);
}

// round 16
// speedup vs baseline: 1.1620x; 1.1620x over previous
#include <cuda_runtime.h>
#include <cstdint>

// ---------------- problem constants ----------------
#define NB    32
#define NC    64
#define HW    56
#define OHW   57
#define LL    3249           // 57*57
#define LLP   3252           // LL padded to multiple of 4 (16B-aligned rows)
#define PP    256            // C*ks*ks
#define NROWS 103968         // NB*LL
#define KCL   512
#define PLSZ  831744         // PP*LL
#define PLSZP 832512         // PP*LLP

// ---------------- scratch ----------------
__device__ float g_cols  [26615808];  // flat [NROWS][256] == [NB][PP][LL], tf32-rounded
__device__ float g_finalP[26640400];  // masked final, PADDED [NB][PP][LLP] (+16 tail pad)
__device__ float g_S     [53231616];  // [NROWS][512] softmax weights (tf32-rounded)
__device__ float g_x2    [NROWS];
__device__ float g_c2    [KCL];
__device__ float g_centT [131072];    // centers^T [256][512] rounded (GEMM2 B: [n=p][k=cl])
__device__ float g_centR [131072];    // centers   [512][256] rounded (GEMM1 B: [n=cl][k=p])
__device__ float g_wR    [32768];     // weight [128][256] rounded    (GEMM3 A)

// ---------------- fast math ----------------
__device__ __forceinline__ float fast_sqrtf(float q) {
    float r = __int_as_float(0x5f3759df - (__float_as_int(q) >> 1));
    r = r * fmaf(-0.5f * q, r * r, 1.5f);
    r = r * fmaf(-0.5f * q, r * r, 1.5f);
    r = r * fmaf(-0.5f * q, r * r, 1.5f);
    float s = q * r;
    return (q > 1e-20f) ? s : 0.0f;
}
__device__ __forceinline__ float fast_expf(float x) {
    x = fmaxf(x, -80.0f);
    float y  = x * 1.44269504088896f;
    float t  = y + 12582912.0f;
    float f  = y - (t - 12582912.0f);
    int   e  = (__float_as_int(t) & 0x7FFFFF) - 0x400000;
    float p  = 1.3333558146e-3f;
    p = fmaf(p, f, 9.6180905e-3f);
    p = fmaf(p, f, 5.5504108665e-2f);
    p = fmaf(p, f, 2.4022650696e-1f);
    p = fmaf(p, f, 6.9314718056e-1f);
    p = fmaf(p, f, 1.0f);
    return p * __int_as_float((e + 127) << 23);
}
__device__ __forceinline__ uint32_t tf32cvt(float x) {
    uint32_t r; asm("cvt.rna.tf32.f32 %0, %1;" : "=r"(r) : "f"(x)); return r;
}
__device__ __forceinline__ float tf32r(float x) { return __uint_as_float(tf32cvt(x)); }

__device__ __forceinline__ void mma_tf32(float* c, const uint32_t* a, uint32_t b0, uint32_t b1) {
    asm volatile("mma.sync.aligned.m16n8k8.row.col.f32.tf32.tf32.f32 "
        "{%0,%1,%2,%3}, {%4,%5,%6,%7}, {%8,%9}, {%0,%1,%2,%3};"
        : "+f"(c[0]), "+f"(c[1]), "+f"(c[2]), "+f"(c[3])
        : "r"(a[0]), "r"(a[1]), "r"(a[2]), "r"(a[3]), "r"(b0), "r"(b1));
}

// ---------------- kernel 1: unfold (warp per flat row) ----------------
__global__ void k_unfold(const float* __restrict__ x) {
    int row = blockIdx.x * 8 + (threadIdx.x >> 5);
    int lane = threadIdx.x & 31;
    float s = 0.f;
    #pragma unroll
    for (int i = 0; i < 8; i++) {
        unsigned g = (unsigned)row * 256u + lane + 32u * i;
        unsigned b   = g / PLSZ;
        unsigned rem = g - b * PLSZ;
        unsigned p   = rem / LL;
        unsigned l   = rem - p * LL;
        unsigned c  = p >> 2, ki = (p >> 1) & 1u, kj = p & 1u;
        unsigned oi = l / OHW, oj = l - oi * OHW;
        int r  = (int)(oi + ki) - 1;
        int cc = (int)(oj + kj) - 1;
        float v = 0.0f;
        if ((unsigned)r < HW && (unsigned)cc < HW)
            v = x[(((b * NC + c) * HW + (unsigned)r) * HW + (unsigned)cc)];
        v = tf32r(v);
        g_cols[g] = v;
        s = fmaf(v, v, s);
    }
    #pragma unroll
    for (int o = 16; o; o >>= 1) s += __shfl_xor_sync(0xffffffffu, s, o);
    if (lane == 0) g_x2[row] = s;
}

// ---------------- kernel 2: |c|^2 ----------------
__global__ void k_c2(const float* __restrict__ cent) {
    int k = blockIdx.x * 8 + (threadIdx.x >> 5);
    int lane = threadIdx.x & 31;
    float s = 0.0f;
    #pragma unroll
    for (int i = 0; i < 8; i++) {
        float v = tf32r(cent[k * 256 + lane + 32 * i]);
        s = fmaf(v, v, s);
    }
    #pragma unroll
    for (int o = 16; o; o >>= 1) s += __shfl_xor_sync(0xffffffffu, s, o);
    if (lane == 0) g_c2[k] = s;
}

// ---------------- kernel 2b: rounded copy + transpose of centers ----------------
__global__ void k_tr(const float* __restrict__ cent) {
    __shared__ float t[32][33];
    int k0 = blockIdx.x * 32, j0 = blockIdx.y * 32;
    int tx = threadIdx.x & 31, ty = threadIdx.x >> 5;
    #pragma unroll
    for (int i = 0; i < 4; i++) {
        float v = tf32r(cent[(k0 + ty + 8 * i) * 256 + j0 + tx]);
        t[ty + 8 * i][tx] = v;
        g_centR[(k0 + ty + 8 * i) * 256 + j0 + tx] = v;
    }
    __syncthreads();
    #pragma unroll
    for (int i = 0; i < 4; i++)
        g_centT[(j0 + ty + 8 * i) * 512 + k0 + tx] = t[tx][ty + 8 * i];
}

// ---------------- kernel 2c: rounded copy of conv weight ----------------
__global__ void k_rw(const float* __restrict__ w) {
    int i = blockIdx.x * 256 + threadIdx.x;
    g_wR[i] = tf32r(w[i]);
}

// ---------------- unified tf32 mma.sync GEMM (512 thr, 3-stage) ----------------
// MODE 1: fused GEMM1+softmax. MT=64, NBLK=512. A=g_cols(K=256), B=g_centR [n][k]
//         (ldmatrix path) -> softmax weights -> g_S.            grid(1625)
// MODE 2: MT=128, NBLK=256. A=g_S(K=512), B=g_centT [n][k] (ldmatrix path)
//         -> blend+mask -> g_finalP [b][p][LLP] (coalesced).    grid(1, 813)
// MODE 3: MT=128, NBLK=256. A=g_wR(K=256), B=g_finalP[b] rows [k=p][n=l]
//         (scalar-frag path, smem [k][260]) -> out + bias.      grid(13, 32)
template<int MT, int NBLK, int KTOT, int MODE>
__global__ __launch_bounds__(512) void k_mma(const float* __restrict__ temp_p,
                                             const float* __restrict__ bias,
                                             float* __restrict__ out)
{
    constexpr int NCH = KTOT / 32;
    constexpr int STG = 3;
    constexpr int AFL = MT * 32;
    constexpr int BFL = (MODE == 3) ? 32 * 260 : NBLK * 32;
    constexpr int WM = MT / 32, WN = 16 / WM;
    constexpr int NTW = NBLK / (WN * 8);
    constexpr int AU = (MT * 8) / 512;
    constexpr int BU = (NBLK * 8) / 512;
    extern __shared__ float sm[];

    const int tid = threadIdx.x;
    const int lane = tid & 31, wid = tid >> 5;
    const int warp_m = wid % WM, warp_n = wid / WM;
    const int g = lane >> 2, kq = lane & 3;

    const int n0 = (MODE == 1) ? 0 : blockIdx.x * NBLK;
    const int m0 = (MODE == 1) ? blockIdx.x * MT : (MODE == 3) ? 0 : blockIdx.y * 128;
    const int bb = (MODE == 3) ? blockIdx.y : 0;

    const float* Aptr = (MODE == 1) ? g_cols : (MODE == 2) ? g_S : g_wR;
    const float* Bptr = (MODE == 1) ? g_centR : (MODE == 2) ? g_centT
                                              : g_finalP + (size_t)bb * PLSZP;

    const uint32_t sA = (uint32_t)__cvta_generic_to_shared(sm);
    const uint32_t sB = sA + STG * AFL * 4;
    float* tail = sm + STG * (AFL + BFL);      // MODE1: c2s[512] + red[1024]

    if constexpr (MODE == 1)
        for (int i = tid; i < 512; i += 512) tail[i] = g_c2[i];

    float acc[2][NTW][4];
    #pragma unroll
    for (int mt = 0; mt < 2; mt++)
        #pragma unroll
        for (int nt = 0; nt < NTW; nt++)
            #pragma unroll
            for (int e = 0; e < 4; e++) acc[mt][nt][e] = 0.0f;

    auto load_stage = [&](int c) {
        const int stg = c % STG;
        #pragma unroll
        for (int i = 0; i < AU; i++) {
            int f = tid + i * 512;
            int row = f >> 3, k4 = f & 7;
            uint32_t dst = sA + (uint32_t)(stg * AFL + row * 32 + ((k4 ^ (row & 7)) << 2)) * 4u;
            int m = m0 + row;
            bool ok = (MODE == 3) || (m < NROWS);
            const float* src = ok ? (Aptr + (size_t)m * KTOT + c * 32 + k4 * 4) : Aptr;
            int sz = ok ? 16 : 0;
            asm volatile("cp.async.cg.shared.global [%0], [%1], 16, %2;"
                         :: "r"(dst), "l"(src), "r"(sz) : "memory");
        }
        if constexpr (MODE == 3) {
            // B rows are [k=p][n=l], stride LLP (16B-aligned); smem [k][260]
            #pragma unroll
            for (int i = 0; i < BU; i++) {
                int f = tid + i * 512;
                int k = f >> 6, n4 = f & 63;
                uint32_t dst = sB + (uint32_t)(stg * BFL + k * 260 + n4 * 4) * 4u;
                int n = n0 + n4 * 4;
                bool ok = (n < LL);   // n<LL => 16B read ends <=3251 < LLP, in-row
                const float* src = ok ? (Bptr + (size_t)(c * 32 + k) * LLP + n) : Bptr;
                int sz = ok ? 16 : 0;
                asm volatile("cp.async.cg.shared.global [%0], [%1], 16, %2;"
                             :: "r"(dst), "l"(src), "r"(sz) : "memory");
            }
        } else {
            #pragma unroll
            for (int i = 0; i < BU; i++) {
                int f = tid + i * 512;
                int row = f >> 3, k4 = f & 7;
                uint32_t dst = sB + (uint32_t)(stg * BFL + row * 32 + ((k4 ^ (row & 7)) << 2)) * 4u;
                int n = n0 + row;
                const float* src = Bptr + (size_t)n * KTOT + c * 32 + k4 * 4;
                asm volatile("cp.async.cg.shared.global [%0], [%1], 16;"
                             :: "r"(dst), "l"(src) : "memory");
            }
        }
        asm volatile("cp.async.commit_group;" ::: "memory");
    };

    auto compute = [&](int c) {
        const uint32_t Ab = sA + (uint32_t)((c % STG) * AFL) * 4u;
        const int arow_base = warp_m * 32 + (lane & 15);
        const int a_hi = lane >> 4;
        #pragma unroll
        for (int s = 0; s < 4; s++) {
            uint32_t af[2][4];
            #pragma unroll
            for (int mt = 0; mt < 2; mt++) {
                int row = arow_base + mt * 16;
                int k4 = 2 * s + a_hi;
                uint32_t addr = Ab + (uint32_t)(row * 32 + ((k4 ^ (row & 7)) << 2)) * 4u;
                asm volatile("ldmatrix.sync.aligned.m8n8.x4.shared.b16 {%0,%1,%2,%3}, [%4];"
                    : "=r"(af[mt][0]), "=r"(af[mt][1]), "=r"(af[mt][2]), "=r"(af[mt][3])
                    : "r"(addr));
            }
            if constexpr (MODE == 3) {
                const float* Bbf = sm + STG * AFL + (c % STG) * BFL;
                uint32_t bfr[4][4];
                #pragma unroll
                for (int np = 0; np < 4; np++) {
                    #pragma unroll
                    for (int wch = 0; wch < 2; wch++) {
                        int n = warp_n * 64 + (np * 2 + wch) * 8 + g;
                        bfr[np][wch * 2 + 0] = __float_as_uint(Bbf[(s * 8 + kq) * 260 + n]);
                        bfr[np][wch * 2 + 1] = __float_as_uint(Bbf[(s * 8 + kq + 4) * 260 + n]);
                    }
                }
                #pragma unroll
                for (int mt = 0; mt < 2; mt++)
                    #pragma unroll
                    for (int np = 0; np < 4; np++) {
                        mma_tf32(acc[mt][np * 2],     af[mt], bfr[np][0], bfr[np][1]);
                        mma_tf32(acc[mt][np * 2 + 1], af[mt], bfr[np][2], bfr[np][3]);
                    }
            } else {
                const uint32_t Bb = sB + (uint32_t)((c % STG) * BFL) * 4u;
                const int brow_lane = lane & 7;
                const int b_grp_hi = lane >> 4;
                const int b_k_hi = (lane >> 3) & 1;
                uint32_t bf[NTW][2];
                #pragma unroll
                for (int p2 = 0; p2 < NTW / 2; p2++) {
                    int n = warp_n * (NTW * 8) + (2 * p2 + b_grp_hi) * 8 + brow_lane;
                    int k4 = 2 * s + b_k_hi;
                    uint32_t addr = Bb + (uint32_t)(n * 32 + ((k4 ^ (n & 7)) << 2)) * 4u;
                    asm volatile("ldmatrix.sync.aligned.m8n8.x4.shared.b16 {%0,%1,%2,%3}, [%4];"
                        : "=r"(bf[2 * p2][0]), "=r"(bf[2 * p2][1]),
                          "=r"(bf[2 * p2 + 1][0]), "=r"(bf[2 * p2 + 1][1])
                        : "r"(addr));
                }
                #pragma unroll
                for (int mt = 0; mt < 2; mt++)
                    #pragma unroll
                    for (int g8 = 0; g8 < NTW; g8++)
                        mma_tf32(acc[mt][g8], af[mt], bf[g8][0], bf[g8][1]);
            }
        }
    };

    load_stage(0); load_stage(1);
    for (int c = 0; c < NCH; c++) {
        if (c + 2 < NCH) {
            load_stage(c + 2);
            asm volatile("cp.async.wait_group 2;" ::: "memory");
        } else {
            asm volatile("cp.async.wait_group 0;" ::: "memory");
        }
        __syncthreads();
        compute(c);
        __syncthreads();
    }

    // ---------------- epilogues ----------------
    if constexpr (MODE == 1) {
        const float temp = *temp_p;
        float* c2s = tail;
        float* redm = tail + 512;        // [64 rows][8 warp_n]
        float* reds = tail + 1024;
        #pragma unroll
        for (int mt = 0; mt < 2; mt++)
            #pragma unroll
            for (int half = 0; half < 2; half++) {
                int rloc = warp_m * 32 + mt * 16 + g + 8 * half;
                int r = m0 + rloc;
                float x2 = (r < NROWS) ? g_x2[r] : 0.f;
                float mx = -1e30f;
                #pragma unroll
                for (int nt = 0; nt < NTW; nt++)
                    #pragma unroll
                    for (int e = 0; e < 2; e++) {
                        int col = warp_n * (NTW * 8) + nt * 8 + kq * 2 + e;
                        float q = fmaxf(fmaf(-2.f, acc[mt][nt][half * 2 + e], x2 + c2s[col]), 0.f);
                        float sc = -fast_sqrtf(q) * temp;
                        acc[mt][nt][half * 2 + e] = sc;
                        mx = fmaxf(mx, sc);
                    }
                mx = fmaxf(mx, __shfl_xor_sync(0xffffffffu, mx, 1));
                mx = fmaxf(mx, __shfl_xor_sync(0xffffffffu, mx, 2));
                if (kq == 0) redm[rloc * 8 + warp_n] = mx;
            }
        __syncthreads();
        #pragma unroll
        for (int mt = 0; mt < 2; mt++)
            #pragma unroll
            for (int half = 0; half < 2; half++) {
                int rloc = warp_m * 32 + mt * 16 + g + 8 * half;
                float m8 = -1e30f;
                #pragma unroll
                for (int j = 0; j < 8; j++) m8 = fmaxf(m8, redm[rloc * 8 + j]);
                float sum = 0.f;
                #pragma unroll
                for (int nt = 0; nt < NTW; nt++)
                    #pragma unroll
                    for (int e = 0; e < 2; e++) {
                        float v = fast_expf(acc[mt][nt][half * 2 + e] - m8);
                        acc[mt][nt][half * 2 + e] = v;
                        sum += v;
                    }
                sum += __shfl_xor_sync(0xffffffffu, sum, 1);
                sum += __shfl_xor_sync(0xffffffffu, sum, 2);
                if (kq == 0) reds[rloc * 8 + warp_n] = sum;
            }
        __syncthreads();
        #pragma unroll
        for (int mt = 0; mt < 2; mt++)
            #pragma unroll
            for (int half = 0; half < 2; half++) {
                int rloc = warp_m * 32 + mt * 16 + g + 8 * half;
                int r = m0 + rloc;
                if (r >= NROWS) continue;
                float denom = 0.f;
                #pragma unroll
                for (int j = 0; j < 8; j++) denom += reds[rloc * 8 + j];
                float inv = 1.0f / denom;
                #pragma unroll
                for (int nt = 0; nt < NTW; nt++) {
                    int col = warp_n * (NTW * 8) + nt * 8 + kq * 2;
                    float2 v = make_float2(tf32r(acc[mt][nt][half * 2] * inv),
                                           tf32r(acc[mt][nt][half * 2 + 1] * inv));
                    *(float2*)&g_S[(size_t)r * 512 + col] = v;
                }
            }
    } else if constexpr (MODE == 2) {
        const float temp = *temp_p;
        const float wT = temp / (temp + 1.0f), wF = 1.0f / (temp + 1.0f);
        #pragma unroll
        for (int mt = 0; mt < 2; mt++)
            #pragma unroll
            for (int half = 0; half < 2; half++) {
                int r = m0 + (warp_m * 2 + mt) * 16 + g + 8 * half;
                if (r >= NROWS) continue;
                unsigned rl = (unsigned)r % LL;
                unsigned b  = (unsigned)r / LL;
                size_t dstb = (size_t)b * PLSZP;
                #pragma unroll
                for (int nt = 0; nt < NTW; nt++) {
                    int j = n0 + warp_n * (NTW * 8) + nt * 8 + kq * 2;
                    #pragma unroll
                    for (int e = 0; e < 2; e++) {
                        unsigned rem = rl * 256u + (unsigned)(j + e);
                        unsigned p = rem / LL;
                        unsigned l = rem - p * LL;
                        unsigned lm = l % OHW;
                        unsigned ki = (p >> 1) & 1u, kj = p & 1u;
                        bool masked = (ki == 0u && l < OHW) || (ki == 1u && l >= 3192u) ||
                                      (kj == 0u && lm == 0u) || (kj == 1u && lm == 56u);
                        float av = acc[mt][nt][half * 2 + e];
                        float val = masked ? 0.0f
                            : fmaf(wT, av, wF * g_cols[(size_t)r * 256 + j + e]);
                        g_finalP[dstb + (size_t)p * LLP + l] = tf32r(val);   // ~linear in rem: coalesced
                    }
                }
            }
    } else {
        #pragma unroll
        for (int mt = 0; mt < 2; mt++)
            #pragma unroll
            for (int half = 0; half < 2; half++) {
                int oc = (warp_m * 2 + mt) * 16 + g + 8 * half;
                float bs = bias[oc];
                #pragma unroll
                for (int nt = 0; nt < NTW; nt++) {
                    int l = n0 + warp_n * (NTW * 8) + nt * 8 + kq * 2;
                    #pragma unroll
                    for (int e = 0; e < 2; e++) {
                        if (l + e < LL)
                            out[((size_t)bb * 128 + oc) * LL + l + e] =
                                acc[mt][nt][half * 2 + e] + bs;
                    }
                }
            }
    }
}

// ---------------- launcher ----------------
extern "C" void kernel_launch(void* const* d_in, const int* in_sizes, int n_in,
                              void* d_out, int out_size) {
    const float* x    = (const float*)d_in[0];
    const float* w    = (const float*)d_in[1];
    const float* bias = (const float*)d_in[2];
    const float* cent = (const float*)d_in[3];
    const float* temp = (const float*)d_in[4];
    float* out = (float*)d_out;

    const int SM1 = 3 * (64 * 32 + 512 * 32) * 4 + 6144;    // 227328
    const int SM2 = 3 * (128 * 32 + 256 * 32) * 4;           // 147456
    const int SM3 = 3 * (128 * 32 + 32 * 260) * 4;           // 148992
    cudaFuncSetAttribute(k_mma<64, 512, 256, 1>,
                         cudaFuncAttributeMaxDynamicSharedMemorySize, SM1);
    cudaFuncSetAttribute(k_mma<128, 256, 512, 2>,
                         cudaFuncAttributeMaxDynamicSharedMemorySize, SM2);
    cudaFuncSetAttribute(k_mma<128, 256, 256, 3>,
                         cudaFuncAttributeMaxDynamicSharedMemorySize, SM3);

    k_c2<<<64, 256>>>(cent);
    k_tr<<<dim3(16, 8), 256>>>(cent);
    k_rw<<<128, 256>>>(w);
    k_unfold<<<12996, 256>>>(x);                                      // profiled slot (#3)
    k_mma<64, 512, 256, 1><<<1625, 512, SM1>>>(temp, bias, out);
    k_mma<128, 256, 512, 2><<<dim3(1, 813), 512, SM2>>>(temp, bias, out);
    k_mma<128, 256, 256, 3><<<dim3(13, 32), 512, SM3>>>(temp, bias, out);
}

// round 17
// speedup vs baseline: 1.1899x; 1.0240x over previous
#include <cuda_runtime.h>
#include <cstdint>

// ---------------- problem constants ----------------
#define NB    32
#define NC    64
#define HW    56
#define OHW   57
#define LL    3249           // 57*57
#define LLP   3252           // LL padded to multiple of 4 (16B-aligned rows)
#define PP    256            // C*ks*ks
#define NROWS 103968         // NB*LL
#define KCL   512
#define PLSZ  831744         // PP*LL
#define PLSZP 832512         // PP*LLP

// ---------------- scratch ----------------
__device__ float g_cols  [26615808];  // flat [NROWS][256] == [NB][PP][LL], tf32-rounded
__device__ float g_finalP[26640400];  // masked final, PADDED [NB][PP][LLP] (+16 tail pad)
__device__ float g_S     [53231616];  // [NROWS][512] softmax weights (tf32-rounded)
__device__ float g_c2    [KCL];
__device__ float g_centT [131072];    // centers^T [256][512] rounded (GEMM2 B: [n=p][k=cl])
__device__ float g_centR [131072];    // centers   [512][256] rounded (GEMM1 B: [n=cl][k=p])
__device__ float g_wR    [32768];     // weight [128][256] rounded    (GEMM3 A)

// ---------------- fast math ----------------
__device__ __forceinline__ float fast_sqrtf(float q) {
    float r = __int_as_float(0x5f3759df - (__float_as_int(q) >> 1));
    r = r * fmaf(-0.5f * q, r * r, 1.5f);
    r = r * fmaf(-0.5f * q, r * r, 1.5f);
    r = r * fmaf(-0.5f * q, r * r, 1.5f);
    float s = q * r;
    return (q > 1e-20f) ? s : 0.0f;
}
__device__ __forceinline__ float fast_expf(float x) {
    x = fmaxf(x, -80.0f);
    float y  = x * 1.44269504088896f;
    float t  = y + 12582912.0f;
    float f  = y - (t - 12582912.0f);
    int   e  = (__float_as_int(t) & 0x7FFFFF) - 0x400000;
    float p  = 1.3333558146e-3f;
    p = fmaf(p, f, 9.6180905e-3f);
    p = fmaf(p, f, 5.5504108665e-2f);
    p = fmaf(p, f, 2.4022650696e-1f);
    p = fmaf(p, f, 6.9314718056e-1f);
    p = fmaf(p, f, 1.0f);
    return p * __int_as_float((e + 127) << 23);
}
__device__ __forceinline__ uint32_t tf32cvt(float x) {
    uint32_t r; asm("cvt.rna.tf32.f32 %0, %1;" : "=r"(r) : "f"(x)); return r;
}
__device__ __forceinline__ float tf32r(float x) { return __uint_as_float(tf32cvt(x)); }

__device__ __forceinline__ void mma_tf32(float* c, const uint32_t* a, uint32_t b0, uint32_t b1) {
    asm volatile("mma.sync.aligned.m16n8k8.row.col.f32.tf32.tf32.f32 "
        "{%0,%1,%2,%3}, {%4,%5,%6,%7}, {%8,%9}, {%0,%1,%2,%3};"
        : "+f"(c[0]), "+f"(c[1]), "+f"(c[2]), "+f"(c[3])
        : "r"(a[0]), "r"(a[1]), "r"(a[2]), "r"(a[3]), "r"(b0), "r"(b1));
}

// ---------------- kernel 1: unfold v2 (division-free, block per (b,oi)) ----------------
// block: 256 thr = 4 p-subgroups x 64 oj-lanes; loop 64 p-groups.
// p = it*4 + sub: c = it, ki = sub>>1, kj = sub&1.
__global__ void k_unfold(const float* __restrict__ x) {
    const int oi  = blockIdx.x;          // 0..56
    const int b   = blockIdx.y;          // 0..31
    const int sub = threadIdx.x >> 6;    // 0..3
    const int oj  = threadIdx.x & 63;
    if (oj >= OHW) return;
    const int ki = sub >> 1, kj = sub & 1;
    const int r  = oi + ki - 1;
    const int cc = oj + kj - 1;
    const bool valid = ((unsigned)r < HW) && ((unsigned)cc < HW);
    const float* xsrc = x + (((size_t)(b * NC) * HW + r) * HW + cc);  // + c*3136
    float* dst = g_cols + ((size_t)(b * 256 + sub) * LL + oi * OHW + oj);  // + it*4*LL
    #pragma unroll 8
    for (int it = 0; it < 64; it++) {
        float v = valid ? xsrc[it * (HW * HW)] : 0.0f;
        dst[(size_t)it * 4 * LL] = tf32r(v);
    }
}

// ---------------- kernel 2: |c|^2 ----------------
__global__ void k_c2(const float* __restrict__ cent) {
    int k = blockIdx.x * 8 + (threadIdx.x >> 5);
    int lane = threadIdx.x & 31;
    float s = 0.0f;
    #pragma unroll
    for (int i = 0; i < 8; i++) {
        float v = tf32r(cent[k * 256 + lane + 32 * i]);
        s = fmaf(v, v, s);
    }
    #pragma unroll
    for (int o = 16; o; o >>= 1) s += __shfl_xor_sync(0xffffffffu, s, o);
    if (lane == 0) g_c2[k] = s;
}

// ---------------- kernel 2b: rounded copy + transpose of centers ----------------
__global__ void k_tr(const float* __restrict__ cent) {
    __shared__ float t[32][33];
    int k0 = blockIdx.x * 32, j0 = blockIdx.y * 32;
    int tx = threadIdx.x & 31, ty = threadIdx.x >> 5;
    #pragma unroll
    for (int i = 0; i < 4; i++) {
        float v = tf32r(cent[(k0 + ty + 8 * i) * 256 + j0 + tx]);
        t[ty + 8 * i][tx] = v;
        g_centR[(k0 + ty + 8 * i) * 256 + j0 + tx] = v;
    }
    __syncthreads();
    #pragma unroll
    for (int i = 0; i < 4; i++)
        g_centT[(j0 + ty + 8 * i) * 512 + k0 + tx] = t[tx][ty + 8 * i];
}

// ---------------- kernel 2c: rounded copy of conv weight ----------------
__global__ void k_rw(const float* __restrict__ w) {
    int i = blockIdx.x * 256 + threadIdx.x;
    g_wR[i] = tf32r(w[i]);
}

// ---------------- unified tf32 mma.sync GEMM (512 thr, 3-stage, single-sync) -------
// MODE 1: fused GEMM1+softmax (x2 computed from A fragments). MT=64, NBLK=512.
//         A=g_cols(K=256), B=g_centR [n][k] (ldmatrix) -> g_S.  grid(1625)
// MODE 2: MT=128, NBLK=256. A=g_S(K=512), B=g_centT [n][k] (ldmatrix)
//         -> blend+mask -> g_finalP [b][p][LLP] (coalesced).    grid(1, 813)
// MODE 3: MT=128, NBLK=256. A=g_wR(K=256), B=g_finalP[b] rows [k=p][n=l]
//         (scalar-frag path, smem [k][260]) -> out + bias.      grid(13, 32)
template<int MT, int NBLK, int KTOT, int MODE>
__global__ __launch_bounds__(512) void k_mma(const float* __restrict__ temp_p,
                                             const float* __restrict__ bias,
                                             float* __restrict__ out)
{
    constexpr int NCH = KTOT / 32;
    constexpr int STG = 3;
    constexpr int AFL = MT * 32;
    constexpr int BFL = (MODE == 3) ? 32 * 260 : NBLK * 32;
    constexpr int WM = MT / 32, WN = 16 / WM;
    constexpr int NTW = NBLK / (WN * 8);
    constexpr int AU = (MT * 8) / 512;
    constexpr int BU = (NBLK * 8) / 512;
    extern __shared__ float sm[];

    const int tid = threadIdx.x;
    const int lane = tid & 31, wid = tid >> 5;
    const int warp_m = wid % WM, warp_n = wid / WM;
    const int g = lane >> 2, kq = lane & 3;

    const int n0 = (MODE == 1) ? 0 : blockIdx.x * NBLK;
    const int m0 = (MODE == 1) ? blockIdx.x * MT : (MODE == 3) ? 0 : blockIdx.y * 128;
    const int bb = (MODE == 3) ? blockIdx.y : 0;

    const float* Aptr = (MODE == 1) ? g_cols : (MODE == 2) ? g_S : g_wR;
    const float* Bptr = (MODE == 1) ? g_centR : (MODE == 2) ? g_centT
                                              : g_finalP + (size_t)bb * PLSZP;

    const uint32_t sA = (uint32_t)__cvta_generic_to_shared(sm);
    const uint32_t sB = sA + STG * AFL * 4;
    float* tail = sm + STG * (AFL + BFL);      // MODE1: c2s[512] + red[1024]

    if constexpr (MODE == 1)
        for (int i = tid; i < 512; i += 512) tail[i] = g_c2[i];

    float acc[2][NTW][4];
    #pragma unroll
    for (int mt = 0; mt < 2; mt++)
        #pragma unroll
        for (int nt = 0; nt < NTW; nt++)
            #pragma unroll
            for (int e = 0; e < 4; e++) acc[mt][nt][e] = 0.0f;

    // MODE1: per-thread row |x|^2 partials from A fragments. [mt][row-half]
    float sq[2][2] = {{0.f, 0.f}, {0.f, 0.f}};

    auto load_stage = [&](int c) {
        const int stg = c % STG;
        #pragma unroll
        for (int i = 0; i < AU; i++) {
            int f = tid + i * 512;
            int row = f >> 3, k4 = f & 7;
            uint32_t dst = sA + (uint32_t)(stg * AFL + row * 32 + ((k4 ^ (row & 7)) << 2)) * 4u;
            int m = m0 + row;
            bool ok = (MODE == 3) || (m < NROWS);
            const float* src = ok ? (Aptr + (size_t)m * KTOT + c * 32 + k4 * 4) : Aptr;
            int sz = ok ? 16 : 0;
            asm volatile("cp.async.cg.shared.global [%0], [%1], 16, %2;"
                         :: "r"(dst), "l"(src), "r"(sz) : "memory");
        }
        if constexpr (MODE == 3) {
            #pragma unroll
            for (int i = 0; i < BU; i++) {
                int f = tid + i * 512;
                int k = f >> 6, n4 = f & 63;
                uint32_t dst = sB + (uint32_t)(stg * BFL + k * 260 + n4 * 4) * 4u;
                int n = n0 + n4 * 4;
                bool ok = (n < LL);
                const float* src = ok ? (Bptr + (size_t)(c * 32 + k) * LLP + n) : Bptr;
                int sz = ok ? 16 : 0;
                asm volatile("cp.async.cg.shared.global [%0], [%1], 16, %2;"
                             :: "r"(dst), "l"(src), "r"(sz) : "memory");
            }
        } else {
            #pragma unroll
            for (int i = 0; i < BU; i++) {
                int f = tid + i * 512;
                int row = f >> 3, k4 = f & 7;
                uint32_t dst = sB + (uint32_t)(stg * BFL + row * 32 + ((k4 ^ (row & 7)) << 2)) * 4u;
                int n = n0 + row;
                const float* src = Bptr + (size_t)n * KTOT + c * 32 + k4 * 4;
                asm volatile("cp.async.cg.shared.global [%0], [%1], 16;"
                             :: "r"(dst), "l"(src) : "memory");
            }
        }
        asm volatile("cp.async.commit_group;" ::: "memory");
    };

    auto compute = [&](int c) {
        const uint32_t Ab = sA + (uint32_t)((c % STG) * AFL) * 4u;
        const int arow_base = warp_m * 32 + (lane & 15);
        const int a_hi = lane >> 4;
        #pragma unroll
        for (int s = 0; s < 4; s++) {
            uint32_t af[2][4];
            #pragma unroll
            for (int mt = 0; mt < 2; mt++) {
                int row = arow_base + mt * 16;
                int k4 = 2 * s + a_hi;
                uint32_t addr = Ab + (uint32_t)(row * 32 + ((k4 ^ (row & 7)) << 2)) * 4u;
                asm volatile("ldmatrix.sync.aligned.m8n8.x4.shared.b16 {%0,%1,%2,%3}, [%4];"
                    : "=r"(af[mt][0]), "=r"(af[mt][1]), "=r"(af[mt][2]), "=r"(af[mt][3])
                    : "r"(addr));
            }
            if constexpr (MODE == 1) {
                // regs 0,2 -> row g; regs 1,3 -> row g+8 (tf32 bit pattern == float)
                #pragma unroll
                for (int mt = 0; mt < 2; mt++) {
                    float v0 = __uint_as_float(af[mt][0]), v2 = __uint_as_float(af[mt][2]);
                    float v1 = __uint_as_float(af[mt][1]), v3 = __uint_as_float(af[mt][3]);
                    sq[mt][0] = fmaf(v0, v0, fmaf(v2, v2, sq[mt][0]));
                    sq[mt][1] = fmaf(v1, v1, fmaf(v3, v3, sq[mt][1]));
                }
            }
            if constexpr (MODE == 3) {
                const float* Bbf = sm + STG * AFL + (c % STG) * BFL;
                uint32_t bfr[4][4];
                #pragma unroll
                for (int np = 0; np < 4; np++) {
                    #pragma unroll
                    for (int wch = 0; wch < 2; wch++) {
                        int n = warp_n * 64 + (np * 2 + wch) * 8 + g;
                        bfr[np][wch * 2 + 0] = __float_as_uint(Bbf[(s * 8 + kq) * 260 + n]);
                        bfr[np][wch * 2 + 1] = __float_as_uint(Bbf[(s * 8 + kq + 4) * 260 + n]);
                    }
                }
                #pragma unroll
                for (int mt = 0; mt < 2; mt++)
                    #pragma unroll
                    for (int np = 0; np < 4; np++) {
                        mma_tf32(acc[mt][np * 2],     af[mt], bfr[np][0], bfr[np][1]);
                        mma_tf32(acc[mt][np * 2 + 1], af[mt], bfr[np][2], bfr[np][3]);
                    }
            } else {
                const uint32_t Bb = sB + (uint32_t)((c % STG) * BFL) * 4u;
                const int brow_lane = lane & 7;
                const int b_grp_hi = lane >> 4;
                const int b_k_hi = (lane >> 3) & 1;
                uint32_t bf[NTW][2];
                #pragma unroll
                for (int p2 = 0; p2 < NTW / 2; p2++) {
                    int n = warp_n * (NTW * 8) + (2 * p2 + b_grp_hi) * 8 + brow_lane;
                    int k4 = 2 * s + b_k_hi;
                    uint32_t addr = Bb + (uint32_t)(n * 32 + ((k4 ^ (n & 7)) << 2)) * 4u;
                    asm volatile("ldmatrix.sync.aligned.m8n8.x4.shared.b16 {%0,%1,%2,%3}, [%4];"
                        : "=r"(bf[2 * p2][0]), "=r"(bf[2 * p2][1]),
                          "=r"(bf[2 * p2 + 1][0]), "=r"(bf[2 * p2 + 1][1])
                        : "r"(addr));
                }
                #pragma unroll
                for (int mt = 0; mt < 2; mt++)
                    #pragma unroll
                    for (int g8 = 0; g8 < NTW; g8++)
                        mma_tf32(acc[mt][g8], af[mt], bf[g8][0], bf[g8][1]);
            }
        }
    };

    // single-sync 3-stage pipeline:
    // sync proves all warps finished compute(c-1) whose stage == (c+2)%3.
    load_stage(0); load_stage(1);
    for (int c = 0; c < NCH; c++) {
        if (c < NCH - 1) { asm volatile("cp.async.wait_group 1;" ::: "memory"); }
        else             { asm volatile("cp.async.wait_group 0;" ::: "memory"); }
        __syncthreads();
        if (c + 2 < NCH) load_stage(c + 2);
        compute(c);
    }

    // ---------------- epilogues ----------------
    if constexpr (MODE == 1) {
        const float temp = *temp_p;
        float* c2s = tail;
        float* redm = tail + 512;        // [64 rows][8 warp_n]
        float* reds = tail + 1024;
        #pragma unroll
        for (int mt = 0; mt < 2; mt++)
            #pragma unroll
            for (int half = 0; half < 2; half++) {
                int rloc = warp_m * 32 + mt * 16 + g + 8 * half;
                // row |x|^2 from fragment partials: reduce over the kq quad
                float x2 = sq[mt][half];
                x2 += __shfl_xor_sync(0xffffffffu, x2, 1);
                x2 += __shfl_xor_sync(0xffffffffu, x2, 2);
                float mx = -1e30f;
                #pragma unroll
                for (int nt = 0; nt < NTW; nt++)
                    #pragma unroll
                    for (int e = 0; e < 2; e++) {
                        int col = warp_n * (NTW * 8) + nt * 8 + kq * 2 + e;
                        float q = fmaxf(fmaf(-2.f, acc[mt][nt][half * 2 + e], x2 + c2s[col]), 0.f);
                        float sc = -fast_sqrtf(q) * temp;
                        acc[mt][nt][half * 2 + e] = sc;
                        mx = fmaxf(mx, sc);
                    }
                mx = fmaxf(mx, __shfl_xor_sync(0xffffffffu, mx, 1));
                mx = fmaxf(mx, __shfl_xor_sync(0xffffffffu, mx, 2));
                if (kq == 0) redm[rloc * 8 + warp_n] = mx;
            }
        __syncthreads();
        #pragma unroll
        for (int mt = 0; mt < 2; mt++)
            #pragma unroll
            for (int half = 0; half < 2; half++) {
                int rloc = warp_m * 32 + mt * 16 + g + 8 * half;
                float m8 = -1e30f;
                #pragma unroll
                for (int j = 0; j < 8; j++) m8 = fmaxf(m8, redm[rloc * 8 + j]);
                float sum = 0.f;
                #pragma unroll
                for (int nt = 0; nt < NTW; nt++)
                    #pragma unroll
                    for (int e = 0; e < 2; e++) {
                        float v = fast_expf(acc[mt][nt][half * 2 + e] - m8);
                        acc[mt][nt][half * 2 + e] = v;
                        sum += v;
                    }
                sum += __shfl_xor_sync(0xffffffffu, sum, 1);
                sum += __shfl_xor_sync(0xffffffffu, sum, 2);
                if (kq == 0) reds[rloc * 8 + warp_n] = sum;
            }
        __syncthreads();
        #pragma unroll
        for (int mt = 0; mt < 2; mt++)
            #pragma unroll
            for (int half = 0; half < 2; half++) {
                int rloc = warp_m * 32 + mt * 16 + g + 8 * half;
                int r = m0 + rloc;
                if (r >= NROWS) continue;
                float denom = 0.f;
                #pragma unroll
                for (int j = 0; j < 8; j++) denom += reds[rloc * 8 + j];
                float inv = 1.0f / denom;
                #pragma unroll
                for (int nt = 0; nt < NTW; nt++) {
                    int col = warp_n * (NTW * 8) + nt * 8 + kq * 2;
                    float2 v = make_float2(tf32r(acc[mt][nt][half * 2] * inv),
                                           tf32r(acc[mt][nt][half * 2 + 1] * inv));
                    *(float2*)&g_S[(size_t)r * 512 + col] = v;
                }
            }
    } else if constexpr (MODE == 2) {
        const float temp = *temp_p;
        const float wT = temp / (temp + 1.0f), wF = 1.0f / (temp + 1.0f);
        #pragma unroll
        for (int mt = 0; mt < 2; mt++)
            #pragma unroll
            for (int half = 0; half < 2; half++) {
                int r = m0 + (warp_m * 2 + mt) * 16 + g + 8 * half;
                if (r >= NROWS) continue;
                unsigned rl = (unsigned)r % LL;
                unsigned b  = (unsigned)r / LL;
                size_t dstb = (size_t)b * PLSZP;
                #pragma unroll
                for (int nt = 0; nt < NTW; nt++) {
                    int j = n0 + warp_n * (NTW * 8) + nt * 8 + kq * 2;
                    #pragma unroll
                    for (int e = 0; e < 2; e++) {
                        unsigned rem = rl * 256u + (unsigned)(j + e);
                        unsigned p = rem / LL;
                        unsigned l = rem - p * LL;
                        unsigned lm = l % OHW;
                        unsigned ki = (p >> 1) & 1u, kj = p & 1u;
                        bool masked = (ki == 0u && l < OHW) || (ki == 1u && l >= 3192u) ||
                                      (kj == 0u && lm == 0u) || (kj == 1u && lm == 56u);
                        float av = acc[mt][nt][half * 2 + e];
                        float val = masked ? 0.0f
                            : fmaf(wT, av, wF * g_cols[(size_t)r * 256 + j + e]);
                        g_finalP[dstb + (size_t)p * LLP + l] = tf32r(val);
                    }
                }
            }
    } else {
        #pragma unroll
        for (int mt = 0; mt < 2; mt++)
            #pragma unroll
            for (int half = 0; half < 2; half++) {
                int oc = (warp_m * 2 + mt) * 16 + g + 8 * half;
                float bs = bias[oc];
                #pragma unroll
                for (int nt = 0; nt < NTW; nt++) {
                    int l = n0 + warp_n * (NTW * 8) + nt * 8 + kq * 2;
                    #pragma unroll
                    for (int e = 0; e < 2; e++) {
                        if (l + e < LL)
                            out[((size_t)bb * 128 + oc) * LL + l + e] =
                                acc[mt][nt][half * 2 + e] + bs;
                    }
                }
            }
    }
}

// ---------------- launcher ----------------
extern "C" void kernel_launch(void* const* d_in, const int* in_sizes, int n_in,
                              void* d_out, int out_size) {
    const float* x    = (const float*)d_in[0];
    const float* w    = (const float*)d_in[1];
    const float* bias = (const float*)d_in[2];
    const float* cent = (const float*)d_in[3];
    const float* temp = (const float*)d_in[4];
    float* out = (float*)d_out;

    const int SM1 = 3 * (64 * 32 + 512 * 32) * 4 + 6144;    // 227328
    const int SM2 = 3 * (128 * 32 + 256 * 32) * 4;           // 147456
    const int SM3 = 3 * (128 * 32 + 32 * 260) * 4;           // 148992
    cudaFuncSetAttribute(k_mma<64, 512, 256, 1>,
                         cudaFuncAttributeMaxDynamicSharedMemorySize, SM1);
    cudaFuncSetAttribute(k_mma<128, 256, 512, 2>,
                         cudaFuncAttributeMaxDynamicSharedMemorySize, SM2);
    cudaFuncSetAttribute(k_mma<128, 256, 256, 3>,
                         cudaFuncAttributeMaxDynamicSharedMemorySize, SM3);

    k_c2<<<64, 256>>>(cent);
    k_tr<<<dim3(16, 8), 256>>>(cent);
    k_rw<<<128, 256>>>(w);
    k_unfold<<<dim3(57, 32), 256>>>(x);                               // profiled slot (#3)
    k_mma<64, 512, 256, 1><<<1625, 512, SM1>>>(temp, bias, out);
    k_mma<128, 256, 512, 2><<<dim3(1, 813), 512, SM2>>>(temp, bias, out);
    k_mma<128, 256, 256, 3><<<dim3(13, 32), 512, SM3>>>(temp, bias, out);
}